// round 2
// baseline (speedup 1.0000x reference)
#include <cuda_runtime.h>
#include <cuda_bf16.h>

// Canonical coefficient tables for the degree-3 polynomial in 5 variables.
// Written by setup_kernel each launch (deterministic), read by main_kernel.
// Only slots with i<=j<=k are ever written AND read.
__device__ float gC1[5];
__device__ float gC2[5][5];
__device__ float gC3[5][5][5];

// Decode E (55 x 5 exponent rows, each summing to 1..3) and scatter layer[k]
// into the canonical (sorted multi-index) slot. vars[] comes out ascending
// because we iterate j ascending.
__global__ void ExternalForcesSI_setup_kernel(const int* __restrict__ E,
                                              const float* __restrict__ layer) {
    int k = blockIdx.x * blockDim.x + threadIdx.x;
    if (k >= 55) return;
    int vars[3];
    int nv = 0;
    #pragma unroll
    for (int j = 0; j < 5; j++) {
        int c = E[k * 5 + j];
        for (int r = 0; r < c; r++) vars[nv++] = j;
    }
    float coef = layer[k];
    if (nv == 1)      gC1[vars[0]] = coef;
    else if (nv == 2) gC2[vars[0]][vars[1]] = coef;
    else              gC3[vars[0]][vars[1]][vars[2]] = coef;
}

__global__ __launch_bounds__(256, 2)
void ExternalForcesSI_main_kernel(const float4* __restrict__ x,
                                  const float* __restrict__ t,
                                  const float* __restrict__ layer,
                                  const float* __restrict__ omegas,
                                  const float* __restrict__ ef,
                                  float2* __restrict__ out,
                                  int n) {
    // ---- hoist all coefficients into registers (amortized over ~8 rows/thread)
    float c1[5], c2[15], c3[35];
    {
        int q = 0;
        #pragma unroll
        for (int i = 0; i < 5; i++) c1[i] = gC1[i];
        #pragma unroll
        for (int i = 0; i < 5; i++)
            #pragma unroll
            for (int j = i; j < 5; j++) c2[q++] = gC2[i][j];
        q = 0;
        #pragma unroll
        for (int i = 0; i < 5; i++)
            #pragma unroll
            for (int j = i; j < 5; j++)
                #pragma unroll
                for (int k = j; k < 5; k++) c3[q++] = gC3[i][j][k];
    }
    float ctc[5], cts[5];
    #pragma unroll
    for (int j = 0; j < 5; j++) {
        ctc[j] = layer[55 + j];   // cos coefficients
        cts[j] = layer[60 + j];   // sin coefficients
    }
    const float w0 = omegas[0];
    const float w1 = omegas[1];
    const float e0 = ef[0];
    const float e1 = ef[1];

    const int stride = gridDim.x * blockDim.x;
    #pragma unroll 2
    for (int row = blockIdx.x * blockDim.x + threadIdx.x; row < n; row += stride) {
        const float4 xv = x[row];
        const float  tv = t[row];
        const float v[5] = {xv.x, xv.y, xv.z, xv.w, tv};

        // Nested Horner: 55 FMAs evaluate the complete degree-3 polynomial.
        float s = 0.0f;
        int q2 = 0, q3 = 0;
        #pragma unroll
        for (int i = 0; i < 5; i++) {
            float ui = c1[i];
            #pragma unroll
            for (int j = i; j < 5; j++) {
                float tij = c2[q2++];
                #pragma unroll
                for (int k = j; k < 5; k++)
                    tij = fmaf(v[k], c3[q3++], tij);
                ui = fmaf(v[j], tij, ui);
            }
            s = fmaf(v[i], ui, s);
        }

        // Trig library: 10 MUFU ops (small args -> fast-path accuracy ~1e-6).
        #pragma unroll
        for (int j = 0; j < 5; j++) {
            s = fmaf(ctc[j], __cosf(w0 * v[j]), s);
            s = fmaf(cts[j], __sinf(w1 * v[j]), s);
        }

        out[row] = make_float2(s * e0, s * e1);
    }
}

extern "C" void kernel_launch(void* const* d_in, const int* in_sizes, int n_in,
                              void* d_out, int out_size) {
    // metadata order: x, t, layer, omegas, ext_filter, E
    const float4* x      = (const float4*)d_in[0];
    const float*  t      = (const float*)d_in[1];
    const float*  layer  = (const float*)d_in[2];
    const float*  omegas = (const float*)d_in[3];
    const float*  ef     = (const float*)d_in[4];
    const int*    E      = (const int*)d_in[5];
    float2* out = (float2*)d_out;

    const int n = in_sizes[1];  // N_DATA (element count of t)

    ExternalForcesSI_setup_kernel<<<1, 64>>>(E, layer);

    // 131072 threads -> ~8 rows/thread: amortizes the 69-coefficient hoist,
    // float4/float coalesced streaming loads, float2 stores.
    ExternalForcesSI_main_kernel<<<512, 256>>>(x, t, layer, omegas, ef, out, n);
}

// round 3
// speedup vs baseline: 1.1604x; 1.1604x over previous
#include <cuda_runtime.h>
#include <cuda_bf16.h>

// One fused kernel. Each block decodes the E exponent table (55 x 5) into
// canonical Horner coefficient slots in shared memory, hoists them into
// registers, then streams rows with 4 rows in flight per thread.

#define ROWS 4

__global__ __launch_bounds__(256, 2)
void ExternalForcesSI_main_kernel(const float4* __restrict__ x,
                                  const float* __restrict__ t,
                                  const float* __restrict__ layer,
                                  const float* __restrict__ omegas,
                                  const float* __restrict__ ef,
                                  const int*   __restrict__ E,
                                  float2* __restrict__ out,
                                  int n) {
    __shared__ float sC1[5];
    __shared__ float sC2[25];
    __shared__ float sC3[125];
    __shared__ float sTrig[10];

    // ---- block-local decode of E -> canonical coefficient slots ----
    const int tx = threadIdx.x;
    if (tx < 55) {
        int vars[3];
        int nv = 0;
        #pragma unroll
        for (int j = 0; j < 5; j++) {
            int c = E[tx * 5 + j];
            for (int r = 0; r < c; r++) vars[nv++] = j;   // ascending
        }
        float coef = layer[tx];
        if (nv == 1)      sC1[vars[0]] = coef;
        else if (nv == 2) sC2[vars[0] * 5 + vars[1]] = coef;
        else              sC3[(vars[0] * 5 + vars[1]) * 5 + vars[2]] = coef;
    }
    if (tx >= 64 && tx < 74) sTrig[tx - 64] = layer[55 + (tx - 64)];
    __syncthreads();

    // ---- hoist coefficients into registers (static LDS, broadcast) ----
    float c1[5], c2[15], c3[35], ctc[5], cts[5];
    {
        int q2 = 0, q3 = 0;
        #pragma unroll
        for (int i = 0; i < 5; i++) {
            c1[i] = sC1[i];
            ctc[i] = sTrig[i];
            cts[i] = sTrig[5 + i];
            #pragma unroll
            for (int j = i; j < 5; j++) {
                c2[q2++] = sC2[i * 5 + j];
                #pragma unroll
                for (int k = j; k < 5; k++)
                    c3[q3++] = sC3[(i * 5 + j) * 5 + k];
            }
        }
    }
    const float w0 = omegas[0];
    const float w1 = omegas[1];
    const float e0 = ef[0];
    const float e1 = ef[1];

    const int stride = gridDim.x * blockDim.x;
    const int tid = blockIdx.x * blockDim.x + tx;

    for (int i0 = tid; i0 < n; i0 += ROWS * stride) {
        // ---- front-batched loads: up to 2*ROWS independent LDGs in flight ----
        int   idx[ROWS];
        bool  act[ROWS];
        float v[ROWS][5];
        #pragma unroll
        for (int r = 0; r < ROWS; r++) {
            idx[r] = i0 + r * stride;
            act[r] = idx[r] < n;
        }
        #pragma unroll
        for (int r = 0; r < ROWS; r++) {
            float4 xv = act[r] ? x[idx[r]] : make_float4(0.f, 0.f, 0.f, 0.f);
            float  tv = act[r] ? t[idx[r]] : 0.f;
            v[r][0] = xv.x; v[r][1] = xv.y; v[r][2] = xv.z; v[r][3] = xv.w;
            v[r][4] = tv;
        }

        // ---- trig first: 10*ROWS independent MUFUs issue early ----
        float strig[ROWS];
        #pragma unroll
        for (int r = 0; r < ROWS; r++) {
            float ta = 0.f, tb = 0.f;
            #pragma unroll
            for (int j = 0; j < 5; j++) {
                ta = fmaf(ctc[j], __cosf(w0 * v[r][j]), ta);
                tb = fmaf(cts[j], __sinf(w1 * v[r][j]), tb);
            }
            strig[r] = ta + tb;
        }

        // ---- degree-3 Horner: 55 FMAs/row, 5 independent ui chains ----
        float s[ROWS];
        #pragma unroll
        for (int r = 0; r < ROWS; r++) {
            float part[5];
            int q2 = 0, q3 = 0;
            #pragma unroll
            for (int i = 0; i < 5; i++) {
                float ui = c1[i];
                #pragma unroll
                for (int j = i; j < 5; j++) {
                    float tij = c2[q2++];
                    #pragma unroll
                    for (int k = j; k < 5; k++)
                        tij = fmaf(v[r][k], c3[q3++], tij);
                    ui = fmaf(v[r][j], tij, ui);
                }
                part[i] = v[r][i] * ui;
            }
            // tree combine (short chain)
            s[r] = ((part[0] + part[1]) + (part[2] + part[3])) + (part[4] + strig[r]);
        }

        #pragma unroll
        for (int r = 0; r < ROWS; r++)
            if (act[r]) out[idx[r]] = make_float2(s[r] * e0, s[r] * e1);
    }
}

extern "C" void kernel_launch(void* const* d_in, const int* in_sizes, int n_in,
                              void* d_out, int out_size) {
    // metadata order: x, t, layer, omegas, ext_filter, E
    const float4* x      = (const float4*)d_in[0];
    const float*  t      = (const float*)d_in[1];
    const float*  layer  = (const float*)d_in[2];
    const float*  omegas = (const float*)d_in[3];
    const float*  ef     = (const float*)d_in[4];
    const int*    E      = (const int*)d_in[5];
    float2* out = (float2*)d_out;

    const int n = in_sizes[1];  // N_DATA (element count of t)

    // Persistent-style grid: 2 CTAs/SM * 148 SMs. Every block pays the tiny
    // E-decode once; rows are grid-strided with 4 in flight per thread.
    ExternalForcesSI_main_kernel<<<296, 256>>>(x, t, layer, omegas, ef, E, out, n);
}